// round 6
// baseline (speedup 1.0000x reference)
#include <cuda_runtime.h>
#include <cuda_bf16.h>

// N=256 rows, W=512 positions, 3 channels, K=512 buckets.
#define N_ROWS 256
#define WLEN   512
#define K      512
#define BT     64            // 2 warps; 8 elements / thread; 8 buckets / thread
#define EPT    8

// Cross-CTA combine scratch (device globals: no allocations allowed).
__device__ float        g_partial[N_ROWS * 3];
__device__ unsigned int g_cnt[N_ROWS];          // zero-init; atomicInc(...,2) self-resets

// One CTA per (row, channel). Count-only histogram (packed pos|neg<<16),
// packed prefix scan, per-element exact int64 contributions via avg-rank:
//   S_pp = 2Σ_pos v(2PP+cP-p), S_nn = 2Σ_neg v(2PN+cN-q), S_all = 2Σ v(2(PP+PN)+cP+cN-W)
//   loss = S_pp/(p²-p+1) + (1-(S_all-S_pp-S_nn)/(2pq+1)) + S_nn/(q²-q+1)
// Fat-thread shape: 64 threads, float4 loads, vectorized smem, cheap 2-warp barriers.
__global__ void __launch_bounds__(BT)
icl_kernel(const float* __restrict__ a_gt, const float* __restrict__ s_gt,
           const float* __restrict__ e_gt, const float* __restrict__ a_h,
           const float* __restrict__ s_h,  const float* __restrict__ e_h,
           float* __restrict__ out)
{
    __shared__ int       cnt[K];       // cntPos | cntNeg<<16
    __shared__ uint2     meta[K];      // {packed count, packed exclusive prefix}
    __shared__ int       warpAgg[2];
    __shared__ long long red[3][2];

    const int n    = blockIdx.x;
    const int c    = blockIdx.y;
    const int tid  = threadIdx.x;
    const int wid  = tid >> 5, lane = tid & 31;
    const int base = n * WLEN;

    const float* __restrict__ gt = (c == 0) ? a_gt : (c == 1) ? s_gt : e_gt;
    const float* __restrict__ ht = (c == 0) ? a_h  : (c == 1) ? s_h  : e_h;

    // ---- global loads first (4 LDG.128, front-batched MLP) ----
    const float4 hA = ((const float4*)(ht + base))[2 * tid];
    const float4 hB = ((const float4*)(ht + base))[2 * tid + 1];
    const float4 gA = ((const float4*)(gt + base))[2 * tid];
    const float4 gB = ((const float4*)(gt + base))[2 * tid + 1];

    // ---- zero count histogram (2 int4 stores/thread) while loads fly ----
    const int4 z4 = make_int4(0, 0, 0, 0);
    ((int4*)cnt)[tid]      = z4;
    ((int4*)cnt)[tid + BT] = z4;
    __syncthreads();

    float h[EPT] = { hA.x, hA.y, hA.z, hA.w, hB.x, hB.y, hB.z, hB.w };
    const float gv[EPT] = { gA.x, gA.y, gA.z, gA.w, gB.x, gB.y, gB.z, gB.w };

    int  b[EPT];
    bool f[EPT];
    #pragma unroll
    for (int i = 0; i < EPT; ++i) {
        int bi = (int)(h[i] * (float)K);
        b[i] = (bi > K - 1) ? (K - 1) : bi;
        f[i] = (gv[i] > 0.5f);
        atomicAdd(&cnt[b[i]], f[i] ? 1 : (1 << 16));
    }
    __syncthreads();

    // ---- packed count scan (8 buckets/thread, blocked; vector LDS) ----
    const int4 xA = ((const int4*)cnt)[2 * tid];
    const int4 xB = ((const int4*)cnt)[2 * tid + 1];
    const int x[EPT] = { xA.x, xA.y, xA.z, xA.w, xB.x, xB.y, xB.z, xB.w };
    int tsum = 0;
    #pragma unroll
    for (int i = 0; i < EPT; ++i) tsum += x[i];

    int incv = tsum;
    #pragma unroll
    for (int off = 1; off < 32; off <<= 1) {
        const int v = __shfl_up_sync(0xFFFFFFFFu, incv, off);
        if (lane >= off) incv += v;
    }
    if (lane == 31) warpAgg[wid] = incv;
    __syncthreads();

    const int total = warpAgg[0] + warpAgg[1];
    int prefix = ((wid == 1) ? warpAgg[0] : 0) + incv - tsum;  // exclusive, bucket tid*8
    const int p = total & 0xFFFF;
    const int q = total >> 16;

    // meta writeback: 4 × STS.128 ({cnt,prefix} pairs)
    uint4* meta4 = (uint4*)meta;
    #pragma unroll
    for (int i = 0; i < EPT; i += 2) {
        const int pr0 = prefix;
        const int pr1 = prefix + x[i];
        meta4[(tid * EPT + i) >> 1] =
            make_uint4((unsigned)x[i], (unsigned)pr0, (unsigned)x[i + 1], (unsigned)pr1);
        prefix = pr1 + x[i + 1];
    }
    __syncthreads();

    // ---- per-element exact int64 contributions ----
    long long app = 0, ann = 0, aall = 0;
    #pragma unroll
    for (int i = 0; i < EPT; ++i) {
        const uint2 m = meta[b[i]];
        const int cP = (int)(m.x & 0xFFFFu), cN = (int)(m.x >> 16);
        const int PP = (int)(m.y & 0xFFFFu), PN = (int)(m.y >> 16);
        const long long v = (long long)(int)(h[i] * 1073741824.0f);
        if (f[i]) app += v * (long long)(2 * PP + cP - p);
        else      ann += v * (long long)(2 * PN + cN - q);
        aall += v * (long long)(2 * (PP + PN) + (cP + cN) - WLEN);
    }

    // ---- reduce: intra-warp, then 2-entry cross-warp ----
    #pragma unroll
    for (int off = 16; off > 0; off >>= 1) {
        app  += __shfl_down_sync(0xFFFFFFFFu, app,  off);
        ann  += __shfl_down_sync(0xFFFFFFFFu, ann,  off);
        aall += __shfl_down_sync(0xFFFFFFFFu, aall, off);
    }
    if (lane == 0) { red[0][wid] = app; red[1][wid] = ann; red[2][wid] = aall; }
    __syncthreads();

    // ---- fp32 tail + last-block combine ----
    if (tid == 0) {
        const long long Ap = red[0][0] + red[0][1];
        const long long An = red[1][0] + red[1][1];
        const long long Aa = red[2][0] + red[2][1];
        const long long Apn = Aa - Ap - An;        // exact: no cancellation risk
        const float sc = 2.0f / 1073741824.0f;
        const float pf = (float)p, qf = (float)q;
        const float c1 = (sc * (float)Ap)  / (pf * (pf - 1.0f) + 1.0f);
        const float c2 = 1.0f - (sc * (float)Apn) / (2.0f * pf * qf + 1.0f);
        const float c3 = (sc * (float)An)  / (qf * (qf - 1.0f) + 1.0f);

        g_partial[n * 3 + c] = c1 + c2 + c3;
        __threadfence();
        const unsigned int old = atomicInc(&g_cnt[n], 2u);   // wraps 2 -> 0 (replay-safe)
        if (old == 2u) {
            volatile float* gp = g_partial;
            out[n] = gp[n * 3 + 0] + gp[n * 3 + 1] + gp[n * 3 + 2];
        }
    }
}

extern "C" void kernel_launch(void* const* d_in, const int* in_sizes, int n_in,
                              void* d_out, int out_size)
{
    const float* a_gt = (const float*)d_in[0];
    const float* s_gt = (const float*)d_in[1];
    const float* e_gt = (const float*)d_in[2];
    const float* a_h  = (const float*)d_in[3];
    const float* s_h  = (const float*)d_in[4];
    const float* e_h  = (const float*)d_in[5];
    float* out = (float*)d_out;

    dim3 grid(N_ROWS, 3);
    icl_kernel<<<grid, BT>>>(a_gt, s_gt, e_gt, a_h, s_h, e_h, out);
}

// round 7
// speedup vs baseline: 1.3893x; 1.3893x over previous
#include <cuda_runtime.h>
#include <cuda_bf16.h>

// N=256 rows, W=512 positions, 3 channels, K=512 buckets.
#define N_ROWS 256
#define WLEN   512
#define K      512
#define BT     128           // 4 warps; 4 elements / thread; 4 buckets / thread
#define EPT    4
#define NW     (BT / 32)     // 4

// Cross-CTA combine scratch (device globals: no allocations allowed).
__device__ float        g_partial[N_ROWS * 3];
__device__ unsigned int g_cnt[N_ROWS];          // zero-init; atomicInc(...,2) self-resets

// One CTA per (row, channel). Count-only histogram (packed pos|neg<<16),
// packed prefix scan, per-element exact int64 contributions via avg-rank:
//   S_pp = 2Σ_pos v(2PP+cP-p), S_nn = 2Σ_neg v(2PN+cN-q), S_all = 2Σ v(2(PP+PN)+cP+cN-W)
//   loss = S_pp/(p²-p+1) + (1-(S_all-S_pp-S_nn)/(2pq+1)) + S_nn/(q²-q+1)
__global__ void __launch_bounds__(BT)
icl_kernel(const float* __restrict__ a_gt, const float* __restrict__ s_gt,
           const float* __restrict__ e_gt, const float* __restrict__ a_h,
           const float* __restrict__ s_h,  const float* __restrict__ e_h,
           float* __restrict__ out)
{
    __shared__ int       cnt[K];       // cntPos | cntNeg<<16
    __shared__ uint2     meta[K];      // {packed count, packed exclusive prefix}
    __shared__ int       warpAgg[NW];
    __shared__ long long red[3][NW];

    const int n    = blockIdx.x;
    const int c    = blockIdx.y;
    const int tid  = threadIdx.x;
    const int wid  = tid >> 5, lane = tid & 31;
    const int base = n * WLEN;

    const float* __restrict__ gt = (c == 0) ? a_gt : (c == 1) ? s_gt : e_gt;
    const float* __restrict__ ht = (c == 0) ? a_h  : (c == 1) ? s_h  : e_h;

    // ---- global loads first (2 LDG.128, front-batched) ----
    const float4 h4 = ((const float4*)(ht + base))[tid];
    const float4 g4 = ((const float4*)(gt + base))[tid];

    // ---- zero count histogram (one int4 store/thread) while loads fly ----
    ((int4*)cnt)[tid] = make_int4(0, 0, 0, 0);
    __syncthreads();

    const float h[EPT]  = { h4.x, h4.y, h4.z, h4.w };
    const float gv[EPT] = { g4.x, g4.y, g4.z, g4.w };

    int  b[EPT];
    bool f[EPT];
    #pragma unroll
    for (int i = 0; i < EPT; ++i) {
        int bi = (int)(h[i] * (float)K);
        b[i] = (bi > K - 1) ? (K - 1) : bi;
        f[i] = (gv[i] > 0.5f);
        atomicAdd(&cnt[b[i]], f[i] ? 1 : (1 << 16));
    }
    __syncthreads();

    // ---- packed count scan (4 buckets/thread, blocked; one int4 LDS) ----
    const int4 x4 = ((const int4*)cnt)[tid];
    const int x[EPT] = { x4.x, x4.y, x4.z, x4.w };
    const int tsum = x[0] + x[1] + x[2] + x[3];

    int incv = tsum;
    #pragma unroll
    for (int off = 1; off < 32; off <<= 1) {
        const int v = __shfl_up_sync(0xFFFFFFFFu, incv, off);
        if (lane >= off) incv += v;
    }
    if (lane == 31) warpAgg[wid] = incv;
    __syncthreads();

    int wbase = 0, total = 0;
    #pragma unroll
    for (int w = 0; w < NW; ++w) {
        const int v = warpAgg[w];
        if (w < wid) wbase += v;
        total += v;
    }
    int prefix = wbase + incv - tsum;            // packed exclusive prefix (bucket 4*tid)
    const int p = total & 0xFFFF;
    const int q = total >> 16;

    // meta writeback: 2 × STS.128 ({cnt,prefix} pairs)
    {
        uint4* meta4 = (uint4*)meta;
        const int pr0 = prefix;
        const int pr1 = pr0 + x[0];
        const int pr2 = pr1 + x[1];
        const int pr3 = pr2 + x[2];
        meta4[2 * tid]     = make_uint4((unsigned)x[0], (unsigned)pr0,
                                        (unsigned)x[1], (unsigned)pr1);
        meta4[2 * tid + 1] = make_uint4((unsigned)x[2], (unsigned)pr2,
                                        (unsigned)x[3], (unsigned)pr3);
    }
    __syncthreads();

    // ---- per-element exact int64 contributions ----
    long long app = 0, ann = 0, aall = 0;
    #pragma unroll
    for (int i = 0; i < EPT; ++i) {
        const uint2 m = meta[b[i]];
        const int cP = (int)(m.x & 0xFFFFu), cN = (int)(m.x >> 16);
        const int PP = (int)(m.y & 0xFFFFu), PN = (int)(m.y >> 16);
        const long long v = (long long)(int)(h[i] * 1073741824.0f);
        if (f[i]) app += v * (long long)(2 * PP + cP - p);
        else      ann += v * (long long)(2 * PN + cN - q);
        aall += v * (long long)(2 * (PP + PN) + (cP + cN) - WLEN);
    }

    // ---- reduce: intra-warp shuffles, then 4-entry cross-warp ----
    #pragma unroll
    for (int off = 16; off > 0; off >>= 1) {
        app  += __shfl_down_sync(0xFFFFFFFFu, app,  off);
        ann  += __shfl_down_sync(0xFFFFFFFFu, ann,  off);
        aall += __shfl_down_sync(0xFFFFFFFFu, aall, off);
    }
    if (lane == 0) { red[0][wid] = app; red[1][wid] = ann; red[2][wid] = aall; }
    __syncthreads();

    // ---- fp32 tail + last-block combine ----
    if (tid == 0) {
        long long Ap = 0, An = 0, Aa = 0;
        #pragma unroll
        for (int w = 0; w < NW; ++w) { Ap += red[0][w]; An += red[1][w]; Aa += red[2][w]; }
        const long long Apn = Aa - Ap - An;        // exact: no cancellation risk
        const float sc = 2.0f / 1073741824.0f;
        const float pf = (float)p, qf = (float)q;
        const float c1 = (sc * (float)Ap)  / (pf * (pf - 1.0f) + 1.0f);
        const float c2 = 1.0f - (sc * (float)Apn) / (2.0f * pf * qf + 1.0f);
        const float c3 = (sc * (float)An)  / (qf * (qf - 1.0f) + 1.0f);

        g_partial[n * 3 + c] = c1 + c2 + c3;
        __threadfence();
        const unsigned int old = atomicInc(&g_cnt[n], 2u);   // wraps 2 -> 0 (replay-safe)
        if (old == 2u) {
            volatile float* gp = g_partial;
            out[n] = gp[n * 3 + 0] + gp[n * 3 + 1] + gp[n * 3 + 2];
        }
    }
}

extern "C" void kernel_launch(void* const* d_in, const int* in_sizes, int n_in,
                              void* d_out, int out_size)
{
    const float* a_gt = (const float*)d_in[0];
    const float* s_gt = (const float*)d_in[1];
    const float* e_gt = (const float*)d_in[2];
    const float* a_h  = (const float*)d_in[3];
    const float* s_h  = (const float*)d_in[4];
    const float* e_h  = (const float*)d_in[5];
    float* out = (float*)d_out;

    dim3 grid(N_ROWS, 3);
    icl_kernel<<<grid, BT>>>(a_gt, s_gt, e_gt, a_h, s_h, e_h, out);
}